// round 4
// baseline (speedup 1.0000x reference)
#include <cuda_runtime.h>

// B=8, IC=512, H=W=64. Fully fused persistent kernel, 128 blocks x 1024 thr.
//   m[b,j] = sum_c x[b,c,j]*w[c] + cb ; BN(train) ; PReLU -> X
//   Xn = X/sqrt(sum_b X^2); r[b]=(1/64)sum_j Xn; T[j]=sum_b Xn*r[b]
//   g[j]=50/64+128-2T[j]; mask=1/64-0.01*g/(|g|+1e-8); out=x*(1+detal*mask)

#define IC    512
#define HW    4096
#define HW4   1024
#define N4    8192
#define NCH   16
#define CPC   32
#define GRID  128
#define NTHR  1024

__device__ float4   g_part4[NCH * N4];   // 2 MiB scratch
__device__ float4   g_m4[N4];            // m, [b][j4]
__device__ float    g_bsum[8];
__device__ float    g_bsum2[8];
__device__ unsigned g_count = 0;         // barrier arrivals (reset by last arriver)
__device__ unsigned g_phase = 0;         // monotonic epoch (never reset -> replay-safe)

// Device-wide barrier. Safe across graph replays: spinners wait for a phase
// CHANGE (monotonic), and only the last arriver resets the count (no one can
// be spinning on count at that moment).
__device__ __forceinline__ void grid_barrier() {
    __syncthreads();
    if (threadIdx.x == 0) {
        volatile unsigned* vph = &g_phase;
        const unsigned ph = *vph;
        __threadfence();
        const unsigned prev = atomicAdd(&g_count, 1u);
        if (prev == GRID - 1u) {
            g_count = 0u;
            __threadfence();
            atomicAdd(&g_phase, 1u);
        } else {
            while (*vph == ph) {}
        }
        __threadfence();
    }
    __syncthreads();
}

__device__ __forceinline__ float4 bn_prelu4(float4 m, float mu, float rstd,
                                            float ga, float be, float p) {
    float4 X;
    X.x = (m.x - mu) * rstd * ga + be; X.x = (X.x > 0.f) ? X.x : p * X.x;
    X.y = (m.y - mu) * rstd * ga + be; X.y = (X.y > 0.f) ? X.y : p * X.y;
    X.z = (m.z - mu) * rstd * ga + be; X.z = (X.z > 0.f) ? X.z : p * X.z;
    X.w = (m.w - mu) * rstd * ga + be; X.w = (X.w > 0.f) ? X.w : p * X.w;
    return X;
}

__global__ void __launch_bounds__(NTHR, 1)
fused_all(const float4* __restrict__ x4,  const float* __restrict__ w,
          const float* __restrict__ cb,   const float* __restrict__ ga,
          const float* __restrict__ be,   const float* __restrict__ pw,
          const float* __restrict__ dt,   float4* __restrict__ out4)
{
    const int tid = threadIdx.x;
    const int bid = blockIdx.x;
    const int warp = tid >> 5, lane = tid & 31;

    __shared__ float sw[CPC];
    __shared__ float s_red[32], s_red2[32];
    __shared__ float s_mu, s_rstd, s_r[8];
    __shared__ float s_warp[32][8];

    // ---------------- Phase A: channel-partial 1x1 conv -----------------
    {
        const int chunk = bid >> 3;                 // 16 chunks x 8 blocks
        if (tid < CPC) sw[tid] = w[chunk * CPC + tid];
        __syncthreads();
        const int n4 = ((bid & 7) << 10) + tid;     // 0..8191
        const int b  = n4 >> 10;
        const int j4 = n4 & (HW4 - 1);
        const float4* xp = x4 + (size_t)(b * IC + chunk * CPC) * HW4 + j4;

        float4 acc = make_float4(0.f, 0.f, 0.f, 0.f);
        #pragma unroll 8
        for (int c = 0; c < CPC; ++c) {
            const float4 v  = xp[(size_t)c * HW4];
            const float  wc = sw[c];
            acc.x += v.x * wc; acc.y += v.y * wc;
            acc.z += v.z * wc; acc.w += v.w * wc;
        }
        g_part4[chunk * N4 + n4] = acc;
    }
    grid_barrier();

    // ---------------- Phase A2: merge partials + stats (blocks 0-7) -----
    if (bid < 8) {
        const int n4 = (bid << 10) + tid;
        const float c0 = cb[0];
        float4 v = make_float4(c0, c0, c0, c0);
        #pragma unroll
        for (int ch = 0; ch < NCH; ++ch) {
            const float4 p = g_part4[ch * N4 + n4];
            v.x += p.x; v.y += p.y; v.z += p.z; v.w += p.w;
        }
        g_m4[n4] = v;

        float s  = v.x + v.y + v.z + v.w;
        float s2 = v.x*v.x + v.y*v.y + v.z*v.z + v.w*v.w;
        #pragma unroll
        for (int o = 16; o > 0; o >>= 1) {
            s  += __shfl_down_sync(0xffffffffu, s,  o);
            s2 += __shfl_down_sync(0xffffffffu, s2, o);
        }
        if (lane == 0) { s_red[warp] = s; s_red2[warp] = s2; }
        __syncthreads();
        if (tid < 32) {
            s = s_red[tid]; s2 = s_red2[tid];
            #pragma unroll
            for (int o = 16; o > 0; o >>= 1) {
                s  += __shfl_down_sync(0xffffffffu, s,  o);
                s2 += __shfl_down_sync(0xffffffffu, s2, o);
            }
            if (tid == 0) { g_bsum[bid] = s; g_bsum2[bid] = s2; }
        }
    }
    grid_barrier();

    // ---------------- Phase B: scale[j4] in registers (all blocks) ------
    if (tid == 0) {
        float s = 0.f, s2 = 0.f;
        #pragma unroll
        for (int i = 0; i < 8; ++i) { s += g_bsum[i]; s2 += g_bsum2[i]; }
        const float mu  = s  * (1.0f / 32768.0f);
        const float var = s2 * (1.0f / 32768.0f) - mu * mu;
        s_mu = mu; s_rstd = rsqrtf(var + 1e-5f);
    }
    __syncthreads();
    const float mu = s_mu, rstd = s_rstd;
    const float gav = ga[0], bev = be[0], p = pw[0], dtv = dt[0];

    // pass 1: per-lane column norms (thread owns float4 column j4 = tid)
    float4 n2 = make_float4(0.f, 0.f, 0.f, 0.f);
    #pragma unroll
    for (int b = 0; b < 8; ++b) {
        const float4 X = bn_prelu4(g_m4[b * HW4 + tid], mu, rstd, gav, bev, p);
        n2.x += X.x*X.x; n2.y += X.y*X.y; n2.z += X.z*X.z; n2.w += X.w*X.w;
    }
    float4 rs4;
    rs4.x = rsqrtf(n2.x); rs4.y = rsqrtf(n2.y);
    rs4.z = rsqrtf(n2.z); rs4.w = rsqrtf(n2.w);

    // pass 2: rloc[b] = sum over this thread's 4 lanes of Xn
    float rloc[8];
    #pragma unroll
    for (int b = 0; b < 8; ++b) {
        const float4 X = bn_prelu4(g_m4[b * HW4 + tid], mu, rstd, gav, bev, p);
        rloc[b] = X.x*rs4.x + X.y*rs4.y + X.z*rs4.z + X.w*rs4.w;
    }
    #pragma unroll
    for (int b = 0; b < 8; ++b)
        #pragma unroll
        for (int o = 16; o > 0; o >>= 1)
            rloc[b] += __shfl_down_sync(0xffffffffu, rloc[b], o);
    if (lane == 0) {
        #pragma unroll
        for (int b = 0; b < 8; ++b) s_warp[warp][b] = rloc[b];
    }
    __syncthreads();
    if (tid < 8) {
        float a = 0.f;
        #pragma unroll
        for (int wi = 0; wi < 32; ++wi) a += s_warp[wi][tid];
        s_r[tid] = a * (1.0f / 64.0f);
    }
    __syncthreads();

    // pass 3: T per lane -> scale4 (registers)
    float4 t4 = make_float4(0.f, 0.f, 0.f, 0.f);
    #pragma unroll
    for (int b = 0; b < 8; ++b) {
        const float rb = s_r[b];
        const float4 X = bn_prelu4(g_m4[b * HW4 + tid], mu, rstd, gav, bev, p);
        t4.x += X.x * rb; t4.y += X.y * rb; t4.z += X.z * rb; t4.w += X.w * rb;
    }
    float4 sc;
    {
        const float Tx = t4.x * rs4.x, Ty = t4.y * rs4.y;
        const float Tz = t4.z * rs4.z, Tw = t4.w * rs4.w;
        const float gx = 50.0f/64.0f + 128.0f - 2.0f*Tx;
        const float gy = 50.0f/64.0f + 128.0f - 2.0f*Ty;
        const float gz = 50.0f/64.0f + 128.0f - 2.0f*Tz;
        const float gw = 50.0f/64.0f + 128.0f - 2.0f*Tw;
        sc.x = 1.0f + dtv * (1.0f/64.0f - 0.01f * gx / (fabsf(gx) + 1e-8f));
        sc.y = 1.0f + dtv * (1.0f/64.0f - 0.01f * gy / (fabsf(gy) + 1e-8f));
        sc.z = 1.0f + dtv * (1.0f/64.0f - 0.01f * gz / (fabsf(gz) + 1e-8f));
        sc.w = 1.0f + dtv * (1.0f/64.0f - 0.01f * gw / (fabsf(gw) + 1e-8f));
    }

    // ---------------- Phase C: out = x * scale (32 rows per block) ------
    // rows are (b,c) planes: global row in [0,4096), block owns 32 rows.
    {
        const size_t base = (size_t)(bid * 32) * HW4 + tid;
        #pragma unroll
        for (int r = 0; r < 32; r += 8) {
            float4 v[8];
            #pragma unroll
            for (int k = 0; k < 8; ++k) v[k] = x4[base + (size_t)(r + k) * HW4];
            #pragma unroll
            for (int k = 0; k < 8; ++k) {
                v[k].x *= sc.x; v[k].y *= sc.y; v[k].z *= sc.z; v[k].w *= sc.w;
            }
            #pragma unroll
            for (int k = 0; k < 8; ++k) out4[base + (size_t)(r + k) * HW4] = v[k];
        }
    }
}

// ---------------- launch ------------------------------------------------
extern "C" void kernel_launch(void* const* d_in, const int* in_sizes, int n_in,
                              void* d_out, int out_size) {
    const float* x  = (const float*)d_in[0];
    const float* w  = (const float*)d_in[1];
    const float* cb = (const float*)d_in[2];
    const float* ga = (const float*)d_in[3];
    const float* be = (const float*)d_in[4];
    const float* pw = (const float*)d_in[5];
    const float* dt = (const float*)d_in[6];

    fused_all<<<GRID, NTHR>>>((const float4*)x, w, cb, ga, be, pw, dt,
                              (float4*)d_out);
}

// round 7
// speedup vs baseline: 1.1062x; 1.1062x over previous
#include <cuda_runtime.h>

// B=8, IC=512, H=W=64.
//   m[b,j] = sum_c x[b,c,j]*w[c] + cb ; BN(train) ; PReLU -> X
//   Xn = X/sqrt(sum_b X^2); r[b]=(1/64)sum_j Xn; T[j]=sum_b Xn*r[b]
//   g[j]=50/64+128-2T[j]; mask=1/64-0.01*g/(|g|+1e-8); out=x*(1+detal*mask)

#define IC    512
#define HW    4096
#define HW4   1024
#define N4    8192        // 8 * HW4
#define NCH   16
#define CPC   32
#define NROWS 4096        // B*IC planes

__device__ float4 g_part4[NCH * N4];   // 2 MiB scratch
__device__ float4 g_m4[N4];            // m, [b][j4]
__device__ float  g_bsum[32];
__device__ float  g_bsum2[32];
__device__ float4 g_scale4[HW4];

// ---------------- K1: channel-partial 1x1 conv (float4 over j) ----------
// grid (32, NCH), block 256. Thread owns one (b,j4) and 32 channels.
// Full unroll -> deep front-batched LDG.128 stream (high MLP).
__global__ void k1_conv_partial(const float4* __restrict__ x4,
                                const float* __restrict__ w) {
    __shared__ float sw[CPC];
    const int tid = threadIdx.x;
    const int ch  = blockIdx.y;
    const int c0  = ch * CPC;
    if (tid < CPC) sw[tid] = w[c0 + tid];
    __syncthreads();

    const int n4 = blockIdx.x * 256 + tid;     // 0..8191
    const int b  = n4 >> 10;
    const int j4 = n4 & (HW4 - 1);
    const float4* xp = x4 + (size_t)(b * IC + c0) * HW4 + j4;

    float4 acc0 = make_float4(0.f, 0.f, 0.f, 0.f);
    float4 acc1 = make_float4(0.f, 0.f, 0.f, 0.f);
    #pragma unroll
    for (int c = 0; c < CPC; c += 2) {
        const float4 v0 = xp[(size_t)c * HW4];
        const float4 v1 = xp[(size_t)(c + 1) * HW4];
        const float  w0 = sw[c], w1 = sw[c + 1];
        acc0.x += v0.x * w0; acc0.y += v0.y * w0;
        acc0.z += v0.z * w0; acc0.w += v0.w * w0;
        acc1.x += v1.x * w1; acc1.y += v1.y * w1;
        acc1.z += v1.z * w1; acc1.w += v1.w * w1;
    }
    acc0.x += acc1.x; acc0.y += acc1.y; acc0.z += acc1.z; acc0.w += acc1.w;
    g_part4[ch * N4 + n4] = acc0;
}

// ---------------- K1b: merge partials + block stats ---------------------
// grid 32, block 256: each thread merges 16 partial float4s for one n4.
__global__ void k1b_merge(const float* __restrict__ convb) {
    const int tid = threadIdx.x;
    const int n4  = blockIdx.x * 256 + tid;    // 0..8191
    const float cb = convb[0];

    float4 v = make_float4(cb, cb, cb, cb);
    #pragma unroll
    for (int ch = 0; ch < NCH; ++ch) {
        const float4 p = g_part4[ch * N4 + n4];
        v.x += p.x; v.y += p.y; v.z += p.z; v.w += p.w;
    }
    g_m4[n4] = v;

    float s  = v.x + v.y + v.z + v.w;
    float s2 = v.x*v.x + v.y*v.y + v.z*v.z + v.w*v.w;

    __shared__ float rs[8], rs2[8];
    #pragma unroll
    for (int o = 16; o > 0; o >>= 1) {
        s  += __shfl_down_sync(0xffffffffu, s,  o);
        s2 += __shfl_down_sync(0xffffffffu, s2, o);
    }
    const int warp = tid >> 5, lane = tid & 31;
    if (lane == 0) { rs[warp] = s; rs2[warp] = s2; }
    __syncthreads();
    if (tid == 0) {
        float a = 0.f, a2 = 0.f;
        #pragma unroll
        for (int i = 0; i < 8; ++i) { a += rs[i]; a2 += rs2[i]; }
        g_bsum[blockIdx.x] = a; g_bsum2[blockIdx.x] = a2;
    }
}

__device__ __forceinline__ float4 bn_prelu4(float4 m, float mu, float rstd,
                                            float ga, float be, float p) {
    float4 X;
    X.x = (m.x - mu) * rstd * ga + be; X.x = (X.x > 0.f) ? X.x : p * X.x;
    X.y = (m.y - mu) * rstd * ga + be; X.y = (X.y > 0.f) ? X.y : p * X.y;
    X.z = (m.z - mu) * rstd * ga + be; X.z = (X.z > 0.f) ? X.z : p * X.z;
    X.w = (m.w - mu) * rstd * ga + be; X.w = (X.w > 0.f) ? X.w : p * X.w;
    return X;
}

// ---------------- K2: BN + PReLU + col-norm + mask -> scale (1 block) ---
// 1024 threads; thread owns float4 column j4 = tid. Three L2 passes over m
// (128 KB each), no global xn round-trip.
__global__ void __launch_bounds__(1024, 1)
k2_mask(const float* __restrict__ gamma, const float* __restrict__ beta,
        const float* __restrict__ pw,    const float* __restrict__ detal) {
    __shared__ float s_mu, s_rstd, s_r[8];
    __shared__ float s_warp[32][8];

    const int tid = threadIdx.x;
    const int warp = tid >> 5, lane = tid & 31;

    if (tid < 32) {
        float s = g_bsum[tid], s2 = g_bsum2[tid];
        #pragma unroll
        for (int o = 16; o > 0; o >>= 1) {
            s  += __shfl_down_sync(0xffffffffu, s,  o);
            s2 += __shfl_down_sync(0xffffffffu, s2, o);
        }
        if (tid == 0) {
            const float mu  = s  * (1.0f / 32768.0f);
            const float var = s2 * (1.0f / 32768.0f) - mu * mu;
            s_mu = mu; s_rstd = rsqrtf(var + 1e-5f);
        }
    }
    __syncthreads();
    const float mu = s_mu, rstd = s_rstd;
    const float ga = gamma[0], be = beta[0], p = pw[0], dt = detal[0];

    // pass 1: column norms
    float4 n2 = make_float4(0.f, 0.f, 0.f, 0.f);
    #pragma unroll
    for (int b = 0; b < 8; ++b) {
        const float4 X = bn_prelu4(g_m4[b * HW4 + tid], mu, rstd, ga, be, p);
        n2.x += X.x*X.x; n2.y += X.y*X.y; n2.z += X.z*X.z; n2.w += X.w*X.w;
    }
    float4 rs4;
    rs4.x = rsqrtf(n2.x); rs4.y = rsqrtf(n2.y);
    rs4.z = rsqrtf(n2.z); rs4.w = rsqrtf(n2.w);

    // pass 2: r[b]
    float rloc[8];
    #pragma unroll
    for (int b = 0; b < 8; ++b) {
        const float4 X = bn_prelu4(g_m4[b * HW4 + tid], mu, rstd, ga, be, p);
        rloc[b] = X.x*rs4.x + X.y*rs4.y + X.z*rs4.z + X.w*rs4.w;
    }
    #pragma unroll
    for (int b = 0; b < 8; ++b)
        #pragma unroll
        for (int o = 16; o > 0; o >>= 1)
            rloc[b] += __shfl_down_sync(0xffffffffu, rloc[b], o);
    if (lane == 0) {
        #pragma unroll
        for (int b = 0; b < 8; ++b) s_warp[warp][b] = rloc[b];
    }
    __syncthreads();
    if (tid < 8) {
        float a = 0.f;
        #pragma unroll
        for (int wi = 0; wi < 32; ++wi) a += s_warp[wi][tid];
        s_r[tid] = a * (1.0f / 64.0f);
    }
    __syncthreads();

    // pass 3: T -> scale
    float4 t4 = make_float4(0.f, 0.f, 0.f, 0.f);
    #pragma unroll
    for (int b = 0; b < 8; ++b) {
        const float rb = s_r[b];
        const float4 X = bn_prelu4(g_m4[b * HW4 + tid], mu, rstd, ga, be, p);
        t4.x += X.x * rb; t4.y += X.y * rb; t4.z += X.z * rb; t4.w += X.w * rb;
    }
    const float Tx = t4.x * rs4.x, Ty = t4.y * rs4.y;
    const float Tz = t4.z * rs4.z, Tw = t4.w * rs4.w;
    const float gx = 50.0f/64.0f + 128.0f - 2.0f*Tx;
    const float gy = 50.0f/64.0f + 128.0f - 2.0f*Ty;
    const float gz = 50.0f/64.0f + 128.0f - 2.0f*Tz;
    const float gw = 50.0f/64.0f + 128.0f - 2.0f*Tw;
    float4 sc;
    sc.x = 1.0f + dt * (1.0f/64.0f - 0.01f * gx / (fabsf(gx) + 1e-8f));
    sc.y = 1.0f + dt * (1.0f/64.0f - 0.01f * gy / (fabsf(gy) + 1e-8f));
    sc.z = 1.0f + dt * (1.0f/64.0f - 0.01f * gz / (fabsf(gz) + 1e-8f));
    sc.w = 1.0f + dt * (1.0f/64.0f - 0.01f * gw / (fabsf(gw) + 1e-8f));
    g_scale4[tid] = sc;
}

// ---------------- K3: out = x * scale[j], 8 planes per thread -----------
// grid 2048, block 256. Thread t: j4 = t&1023, planes 8g..8g+7.
// __ldcs: x lines are dead after this read (evict-first).
// __stcs: out is write-once (streaming store, don't pollute L2 / evict x).
__global__ void k3_apply(const float4* __restrict__ x4, float4* __restrict__ out4) {
    const int t  = blockIdx.x * 256 + threadIdx.x;   // 0 .. 524287
    const int j4 = t & (HW4 - 1);
    const int g  = t >> 10;                          // plane group 0..511
    const float4 s = g_scale4[j4];
    const size_t base = (size_t)(g * 8) * HW4 + j4;

    float4 v[8];
    #pragma unroll
    for (int k = 0; k < 8; ++k) v[k] = __ldcs(&x4[base + (size_t)k * HW4]);
    #pragma unroll
    for (int k = 0; k < 8; ++k) {
        v[k].x *= s.x; v[k].y *= s.y; v[k].z *= s.z; v[k].w *= s.w;
    }
    #pragma unroll
    for (int k = 0; k < 8; ++k) __stcs(&out4[base + (size_t)k * HW4], v[k]);
}

// ---------------- launch ------------------------------------------------
extern "C" void kernel_launch(void* const* d_in, const int* in_sizes, int n_in,
                              void* d_out, int out_size) {
    const float* x  = (const float*)d_in[0];
    const float* w  = (const float*)d_in[1];
    const float* cb = (const float*)d_in[2];
    const float* ga = (const float*)d_in[3];
    const float* be = (const float*)d_in[4];
    const float* pw = (const float*)d_in[5];
    const float* dt = (const float*)d_in[6];

    dim3 g1(N4 / 256, NCH);
    k1_conv_partial<<<g1, 256>>>((const float4*)x, w);
    k1b_merge<<<32, 256>>>(cb);
    k2_mask<<<1, 1024>>>(ga, be, pw, dt);
    k3_apply<<<2048, 256>>>((const float4*)x, (float4*)d_out);
}